// round 16
// baseline (speedup 1.0000x reference)
#include <cuda_runtime.h>
#include <cuda_fp16.h>
#include <cstdint>
#include <cstddef>

// Problem dims (fixed)
#define S_ROWS  8192      // B*L = 16*512
#define D_MODEL 512
#define D_HALF  256
#define G4      2048      // 4*D_MODEL

#define ZSCALE  2048.0f
#define ZINV    (1.0f / 2048.0f)

// ---------------------------------------------------------------------------
// Scratch (static device arrays — no runtime allocation)
// ---------------------------------------------------------------------------
__device__ __half g_glu[S_ROWS * D_HALF];
__device__ short  g_z[(size_t)S_ROWS * G4];     // gate-interleaved, int16 x2048
__device__ __half g_h0[S_ROWS * D_MODEL];       // ping-pong h buffers (no WAR race)
__device__ __half g_h1[S_ROWS * D_MODEL];
__device__ float  g_c[S_ROWS * D_MODEL];
__device__ __half g_wih_p[G4 * D_MODEL];        // permuted fp16 w_ih
__device__ __half g_whh_p[G4 * D_MODEL];        // permuted fp16 w_hh
__device__ __half g_convw_t[D_HALF * D_MODEL];  // conv_w^T fp16 [c, d]
__device__ __half g_wcomb[G4 * D_HALF];         // w_ih_p @ conv_w  (fp16)
__device__ float  g_bcomb[G4];                  // w_ih·conv_b + b_ih + b_hh (permuted)
__device__ float  g_bsum[G4];                   // b_ih + b_hh, permuted (fp32)

// ---------------------------------------------------------------------------
// Helpers (base PTX only)
// ---------------------------------------------------------------------------
__device__ __forceinline__ uint32_t smem_u32(const void* p) {
    uint32_t a;
    asm("{ .reg .u64 t; cvta.to.shared.u64 t, %1; cvt.u32.u64 %0, t; }" : "=r"(a) : "l"(p));
    return a;
}
__device__ __forceinline__ void cp16(uint32_t dst, const void* src) {
    asm volatile("cp.async.cg.shared.global [%0], [%1], 16;" :: "r"(dst), "l"(src) : "memory");
}
// completion-driven arrival: this thread's outstanding cp.asyncs complete ->
// ONE arrival on the mbarrier. .noinc is load-bearing: the default variant
// increments-then-decrements the expected count (net zero) and deadlocks (R13).
__device__ __forceinline__ void cp_arrive_noinc(uint32_t mbar) {
    asm volatile("cp.async.mbarrier.arrive.noinc.shared::cta.b64 [%0];" :: "r"(mbar) : "memory");
}
__device__ __forceinline__ void mbar_init(uint32_t mbar, uint32_t cnt) {
    asm volatile("mbarrier.init.shared.b64 [%0], %1;" :: "r"(mbar), "r"(cnt) : "memory");
}
__device__ __forceinline__ void mbar_arrive(uint32_t mbar) {
    asm volatile("mbarrier.arrive.shared.b64 _, [%0];" :: "r"(mbar) : "memory");
}
__device__ __forceinline__ void mbar_wait(uint32_t mbar, uint32_t parity) {
    uint32_t done;
    asm volatile(
        "{\n\t.reg .pred p;\n\t"
        "mbarrier.try_wait.parity.acquire.cta.shared::cta.b64 p, [%1], %2;\n\t"
        "selp.b32 %0, 1, 0, p;\n\t}"
        : "=r"(done) : "r"(mbar), "r"(parity) : "memory");
    if (!done) {
        asm volatile(
            "{\n\t.reg .pred P1;\n\t"
            "WAIT_LOOP_%=:\n\t"
            "mbarrier.try_wait.parity.acquire.cta.shared::cta.b64 P1, [%0], %1, 0x989680;\n\t"
            "@P1 bra.uni WAIT_DONE_%=;\n\t"
            "bra.uni WAIT_LOOP_%=;\n\t"
            "WAIT_DONE_%=:\n\t}"
            :: "r"(mbar), "r"(parity) : "memory");
    }
}
__device__ __forceinline__ void ldsm_x4(uint32_t& r0, uint32_t& r1, uint32_t& r2, uint32_t& r3,
                                        uint32_t addr) {
    asm volatile("ldmatrix.sync.aligned.m8n8.x4.shared.b16 {%0,%1,%2,%3}, [%4];"
                 : "=r"(r0), "=r"(r1), "=r"(r2), "=r"(r3) : "r"(addr));
}

// m16n8k16 fp16 MMA, fp32 accumulate: D = A*B + D
__device__ __forceinline__ void mma_f16(float c[4], const uint32_t a[4], const uint32_t b[2]) {
    asm volatile(
        "mma.sync.aligned.m16n8k16.row.col.f32.f16.f16.f32 "
        "{%0,%1,%2,%3}, {%4,%5,%6,%7}, {%8,%9}, {%0,%1,%2,%3};"
        : "+f"(c[0]), "+f"(c[1]), "+f"(c[2]), "+f"(c[3])
        : "r"(a[0]), "r"(a[1]), "r"(a[2]), "r"(a[3]), "r"(b[0]), "r"(b[1]));
}

__device__ __forceinline__ float sigm(float x) { return 1.f / (1.f + __expf(-x)); }
__device__ __forceinline__ short zq(float v) {
    return (short)__float2int_rn(fminf(fmaxf(v, -15.9f), 15.9f) * ZSCALE);
}

// ---------------------------------------------------------------------------
// fp16 tensor-core GEMM (TN): C[m,n] = sum_k A[m*K+k] * Bw[n*K+k] (+bias)
// Block 128x128, 8 warps (2 M x 4 N), warp tile 64x32, BK=64 halves.
// 3-stage cp.async pipeline decoupled via mbarriers:
//   full[s]:  init 256, one .noinc completion-arrival per thread per fill
//   empty[s]: init 8,  one arrival per warp after it finishes computing s
// -> NO __syncthreads in the mainloop; warps skew up to 2 panels.
// Template MODE selects the epilogue at COMPILE TIME (keeps hot MODE 0
// under the 128-reg cap):
//   MODE 0: fused LSTM cell (steps 1..8); MODE 1: plain fp16 C;
//   MODE 3: int16 z + fused LSTM step 0.
// Gate-interleaved B/z layout (col n' = 4d + gate). h_out must not alias A.
// ---------------------------------------------------------------------------
#define BK      64                     // halves per K panel
#define ROW32   36                     // uint32 per smem row (32 data + 4 pad)
#define STAGE32 ((128 + 128) * ROW32)  // 9216 uint32 per stage
#define BARS_OFF (3 * STAGE32 * 4)     // barrier region after stage buffers
#define GEMM_SMEM (BARS_OFF + 64)      // 110656 bytes
#define GTS     136                    // epilogue gate-tile row stride (floats)

template <int MODE>
__global__ __launch_bounds__(256, 2)
void gemm_mma(const __half* __restrict__ A, const __half* __restrict__ Bw,
              void* __restrict__ C, int Nt, int K,
              const float* __restrict__ bias,
              const short* __restrict__ z, const float* __restrict__ bsum,
              const float* __restrict__ c_in, float* __restrict__ c_out,
              __half* __restrict__ h_out_h, float* __restrict__ h_out_f,
              int step, int write_c)
{
    extern __shared__ uint32_t sm32[];
    const int tid  = threadIdx.x;
    const int lane = tid & 31;
    const int wid  = tid >> 5;
    const int g    = lane >> 2;
    const int ctg  = lane & 3;
    const int wm   = (wid & 1) * 64;      // 2 warps along M
    const int wn   = (wid >> 1) * 32;     // 4 warps along N
    const int bm   = blockIdx.y * 128;
    const int bn   = blockIdx.x * 128;
    const int KT   = K / BK;
    const uint32_t sb = smem_u32(sm32);

    const uint32_t fullb  = sb + BARS_OFF;        // full[s]  = fullb  + 8*s
    const uint32_t emptyb = sb + BARS_OFF + 24;   // empty[s] = emptyb + 8*s
    if (tid == 0) {
        #pragma unroll
        for (int s = 0; s < 3; s++) {
            mbar_init(fullb  + 8 * s, 256);
            mbar_init(emptyb + 8 * s, 8);
        }
    }
    __syncthreads();

    // ldmatrix per-lane address offsets (uint32 units) — validated R10/R11
    const uint32_t a_off32 = (uint32_t)(wm + (lane & 7) + ((lane >> 3) & 1) * 8) * ROW32
                           + ((lane >> 4) & 1) * 4;
    const uint32_t b_off32 = (uint32_t)(128 + wn + (lane & 7) + ((lane >> 4) & 1) * 8) * ROW32
                           + ((lane >> 3) & 1) * 4;

    auto load_stage = [&](int kt, int s) {
        const int k0 = kt * BK;
        const uint32_t ab = sb + (uint32_t)s * STAGE32 * 4;
        const uint32_t bb = ab + 128 * ROW32 * 4;
        #pragma unroll
        for (int i = 0; i < 4; i++) {            // A: 128 rows x 8 granules(16B)
            int idx = tid + i * 256;
            int r = idx >> 3, cc = idx & 7;
            cp16(ab + (uint32_t)(r * ROW32 + cc * 4) * 4,
                 A + (size_t)(bm + r) * K + k0 + cc * 8);
        }
        #pragma unroll
        for (int i = 0; i < 4; i++) {            // B: 128 rows x 8 granules
            int idx = tid + i * 256;
            int r = idx >> 3, cc = idx & 7;
            cp16(bb + (uint32_t)(r * ROW32 + cc * 4) * 4,
                 Bw + (size_t)(bn + r) * K + k0 + cc * 8);
        }
    };

    float acc[4][4][4];
    #pragma unroll
    for (int mi = 0; mi < 4; mi++)
        #pragma unroll
        for (int ni = 0; ni < 4; ni++)
            #pragma unroll
            for (int t = 0; t < 4; t++) acc[mi][ni][t] = 0.f;

    // prologue: stages 0,1 in flight
    load_stage(0, 0); cp_arrive_noinc(fullb + 0);
    load_stage(1, 1); cp_arrive_noinc(fullb + 8);

    for (int kt = 0; kt < KT; kt++) {
        const int s = kt % 3, r = kt / 3;
        const int pf = kt + 2;
        if (pf < KT) {
            const int s2 = pf % 3, r2 = pf / 3;
            if (r2 > 0) mbar_wait(emptyb + 8 * s2, (uint32_t)((r2 - 1) & 1));
            load_stage(pf, s2);
            cp_arrive_noinc(fullb + 8 * s2);
        }
        mbar_wait(fullb + 8 * s, (uint32_t)(r & 1));

        const uint32_t stage_addr = sb + (uint32_t)s * STAGE32 * 4;
        const uint32_t a_addr = stage_addr + a_off32 * 4;
        const uint32_t b_addr = stage_addr + b_off32 * 4;

        #pragma unroll
        for (int ks = 0; ks < 4; ks++) {          // 4 x k16 per panel
            uint32_t af[4][4], bf[4][2];
            #pragma unroll
            for (int mi = 0; mi < 4; mi++)
                ldsm_x4(af[mi][0], af[mi][1], af[mi][2], af[mi][3],
                        a_addr + (uint32_t)(mi * 16 * ROW32 + ks * 8) * 4);
            #pragma unroll
            for (int j = 0; j < 2; j++)
                ldsm_x4(bf[2 * j][0], bf[2 * j][1], bf[2 * j + 1][0], bf[2 * j + 1][1],
                        b_addr + (uint32_t)(j * 16 * ROW32 + ks * 8) * 4);
            #pragma unroll
            for (int mi = 0; mi < 4; mi++)
                #pragma unroll
                for (int ni = 0; ni < 4; ni++)
                    mma_f16(acc[mi][ni], af[mi], bf[ni]);
        }
        __syncwarp();
        if (lane == 0) mbar_arrive(emptyb + 8 * s);
    }

    if constexpr (MODE == 0) {
        // ---- fused LSTM epilogue (steps 1..8) ----
        __syncthreads();               // all warps done with stage buffers
        float* smf = (float*)sm32;
        #pragma unroll
        for (int ni = 0; ni < 4; ni++) {
            const int cl = wn + ni * 8 + 2 * ctg;
            #pragma unroll
            for (int mi = 0; mi < 4; mi++) {
                const int rl = wm + mi * 16 + g;
                *(float2*)(smf + (size_t)rl * GTS + cl)       = make_float2(acc[mi][ni][0], acc[mi][ni][1]);
                *(float2*)(smf + (size_t)(rl + 8) * GTS + cl) = make_float2(acc[mi][ni][2], acc[mi][ni][3]);
            }
        }
        __syncthreads();

        const int dn0 = bn >> 2;                     // 32 hidden units per N tile
        #pragma unroll
        for (int it = 0; it < 16; it++) {
            int idx = it * 256 + tid;
            int rl = idx >> 5, dl = idx & 31;
            int s = bm + rl, d = dn0 + dl;
            int l = s & 511, t = l - 8 + step;

            float4 gz;
            if (t >= 0) {
                short4 q = *(const short4*)(z + (size_t)(s - 8 + step) * G4 + 4 * d);
                gz = make_float4(q.x * ZINV, q.y * ZINV, q.z * ZINV, q.w * ZINV);
            } else {
                gz = *(const float4*)(bsum + 4 * d);
            }

            float4 gr = *(const float4*)(smf + (size_t)rl * GTS + 4 * dl);
            float gi = gz.x + gr.x;
            float gf = gz.y + gr.y;
            float gg = gz.z + gr.z;
            float go = gz.w + gr.w;

            float c_prev = c_in[(size_t)s * D_MODEL + d];
            float cn = sigm(gf) * c_prev + sigm(gi) * tanhf(gg);
            float hn = sigm(go) * tanhf(cn);
            if (write_c) c_out[(size_t)s * D_MODEL + d] = cn;
            if (h_out_h) h_out_h[(size_t)s * D_MODEL + d] = __float2half_rn(hn);
            else         h_out_f[(size_t)s * D_MODEL + d] = hn;
        }
    } else if constexpr (MODE == 3) {
        // ---- z-production epilogue + fused LSTM step 0 ----
        __syncthreads();               // stage buffers free
        float* smf = (float*)sm32;
        #pragma unroll
        for (int ni = 0; ni < 4; ni++) {
            const int cl = wn + ni * 8 + 2 * ctg;
            #pragma unroll
            for (int mi = 0; mi < 4; mi++) {
                const int rl = wm + mi * 16 + g;
                *(float2*)(smf + (size_t)rl * GTS + cl)       = make_float2(acc[mi][ni][0], acc[mi][ni][1]);
                *(float2*)(smf + (size_t)(rl + 8) * GTS + cl) = make_float2(acc[mi][ni][2], acc[mi][ni][3]);
            }
        }
        __syncthreads();

        short* Cs = (short*)C;
        const int dn0 = bn >> 2;
        #pragma unroll
        for (int it = 0; it < 16; it++) {
            int idx = it * 256 + tid;
            int rl = idx >> 5, dl = idx & 31;
            int row = bm + rl, d = dn0 + dl;

            float4 gr = *(const float4*)(smf + (size_t)rl * GTS + 4 * dl);
            float4 bb = *(const float4*)(bias + 4 * d);
            float gi = gr.x + bb.x;
            float gf = gr.y + bb.y;
            float gg = gr.z + bb.z;
            float go = gr.w + bb.w;

            // write int16 z (used by steps 1..8)
            short4 q = make_short4(zq(gi), zq(gf), zq(gg), zq(go));
            *(short4*)(Cs + (size_t)row * Nt + 4 * d) = q;

            // fused step 0 for sequence s = row + 8 (same batch only)
            if ((row & 511) < 504) {
                int s = row + 8;
                float cn = sigm(gi) * tanhf(gg);
                float hn = sigm(go) * tanhf(cn);
                c_out[(size_t)s * D_MODEL + d] = cn;
                h_out_h[(size_t)s * D_MODEL + d] = __float2half_rn(hn);
            }
        }
        // sequences with l < 8: step 0 input is zero-padded -> bias-only gates
        if ((bm & 511) == 0) {
            int rl = tid >> 5, dl = tid & 31;     // 8 rows x 32 d
            int s = bm + rl, d = dn0 + dl;
            float4 gz = *(const float4*)(bsum + 4 * d);
            float cn = sigm(gz.x) * tanhf(gz.z);
            float hn = sigm(gz.w) * tanhf(cn);
            c_out[(size_t)s * D_MODEL + d] = cn;
            h_out_h[(size_t)s * D_MODEL + d] = __float2half_rn(hn);
        }
    } else {
        // ---- MODE 1: plain epilogue: bias, write fp16 ----
        #pragma unroll
        for (int ni = 0; ni < 4; ni++) {
            const int col = bn + wn + ni * 8 + 2 * ctg;
            float b0 = 0.f, b1 = 0.f;
            if (bias) { b0 = bias[col]; b1 = bias[col + 1]; }
            #pragma unroll
            for (int mi = 0; mi < 4; mi++) {
                const int row = bm + wm + mi * 16 + g;
                float v0 = acc[mi][ni][0] + b0;
                float v1 = acc[mi][ni][1] + b1;
                float v2 = acc[mi][ni][2] + b0;
                float v3 = acc[mi][ni][3] + b1;
                __half* Ch = (__half*)C;
                *(__half2*)(Ch + (size_t)row * Nt + col)       = __floats2half2_rn(v0, v1);
                *(__half2*)(Ch + (size_t)(row + 8) * Nt + col) = __floats2half2_rn(v2, v3);
            }
        }
    }
}

// ---------------------------------------------------------------------------
// Merged prep kernel: permute+convert recurrent weights to fp16, transpose
// conv_w to fp16 [c, d], bsum, and bias_comb (warp dot-products) — one launch.
// ---------------------------------------------------------------------------
#define WSEG   (G4 * D_MODEL / 4)          // 262144 float4 per weight matrix
#define CSEG   (D_HALF * D_MODEL / 4)      // 32768 (transposed conv, 4 d per item)
#define BSEG   (G4 / 4)                    // 512
#define BCSEG  (G4 * 32)                   // 65536 (one warp per bias_comb entry)
#define PREP_TOTAL (2 * WSEG + CSEG + BSEG + BCSEG)

__global__ void prep_kernel(const float* __restrict__ w_ih, const float* __restrict__ w_hh,
                            const float* __restrict__ conv_w, const float* __restrict__ conv_b,
                            const float* __restrict__ b_ih, const float* __restrict__ b_hh,
                            __half* __restrict__ wihp, __half* __restrict__ whhp,
                            __half* __restrict__ convwt, float* __restrict__ bsum,
                            float* __restrict__ bcomb)
{
    int i = blockIdx.x * blockDim.x + threadIdx.x;
    if (i >= PREP_TOTAL) return;

    if (i < 2 * WSEG) {
        const float* src = (i < WSEG) ? w_ih : w_hh;
        __half* dst = (i < WSEG) ? wihp : whhp;
        int j = (i < WSEG) ? i : i - WSEG;
        int np = j >> 7;                 // dst row (0..2047)
        int c4 = (j & 127) * 4;
        int d = np >> 2, gg = np & 3;
        float4 v = *(const float4*)(src + (size_t)(gg * D_MODEL + d) * D_MODEL + c4);
        __half* o = dst + (size_t)np * D_MODEL + c4;
        *(__half2*)(o)     = __floats2half2_rn(v.x, v.y);
        *(__half2*)(o + 2) = __floats2half2_rn(v.z, v.w);
    } else if (i < 2 * WSEG + CSEG) {
        int j = i - 2 * WSEG;
        int cc = j >> 7;                 // 0..255
        int d0 = (j & 127) * 4;          // 0..508
        float v0 = conv_w[(size_t)(d0 + 0) * D_HALF + cc];
        float v1 = conv_w[(size_t)(d0 + 1) * D_HALF + cc];
        float v2 = conv_w[(size_t)(d0 + 2) * D_HALF + cc];
        float v3 = conv_w[(size_t)(d0 + 3) * D_HALF + cc];
        __half* o = convwt + (size_t)cc * D_MODEL + d0;
        *(__half2*)(o)     = __floats2half2_rn(v0, v1);
        *(__half2*)(o + 2) = __floats2half2_rn(v2, v3);
    } else if (i < 2 * WSEG + CSEG + BSEG) {
        int j = i - 2 * WSEG - CSEG;     // 4 bsum entries
        #pragma unroll
        for (int t = 0; t < 4; t++) {
            int np = j * 4 + t;
            int d = np >> 2, gg = np & 3;
            bsum[np] = b_ih[gg * D_MODEL + d] + b_hh[gg * D_MODEL + d];
        }
    } else {
        // bias_comb: one warp per np (segment base is warp-aligned)
        int j = i - (2 * WSEG + CSEG + BSEG);
        int np = j >> 5;
        int lane = j & 31;
        int dd = np >> 2, gg = np & 3;
        const float* wr = w_ih + (size_t)(gg * D_MODEL + dd) * D_MODEL;
        float s = 0.f;
        #pragma unroll 4
        for (int d = lane; d < D_MODEL; d += 32) s += wr[d] * conv_b[d];
        #pragma unroll
        for (int o = 16; o; o >>= 1) s += __shfl_xor_sync(0xffffffffu, s, o);
        if (lane == 0) bcomb[np] = s + b_ih[gg * D_MODEL + dd] + b_hh[gg * D_MODEL + dd];
    }
}

// ---------------------------------------------------------------------------
// GLU: out[s,c] = fp16(a * sigmoid(b))
// ---------------------------------------------------------------------------
__global__ void glu_kernel(const float* __restrict__ x, __half* __restrict__ out)
{
    int idx = blockIdx.x * blockDim.x + threadIdx.x;
    if (idx >= S_ROWS * D_HALF / 4) return;
    int row = idx / (D_HALF / 4);
    int c4  = (idx % (D_HALF / 4)) * 4;
    const float* xr = x + (size_t)row * D_MODEL;
    float4 a = *(const float4*)(xr + c4);
    float4 b = *(const float4*)(xr + D_HALF + c4);
    __half* o = out + (size_t)row * D_HALF + c4;
    *(__half2*)(o)     = __floats2half2_rn(a.x * sigm(b.x), a.y * sigm(b.y));
    *(__half2*)(o + 2) = __floats2half2_rn(a.z * sigm(b.z), a.w * sigm(b.w));
}

// ---------------------------------------------------------------------------
// Launcher
// ---------------------------------------------------------------------------
extern "C" void kernel_launch(void* const* d_in, const int* in_sizes, int n_in,
                              void* d_out, int out_size)
{
    const float* x      = (const float*)d_in[0];
    const float* conv_w = (const float*)d_in[1];
    const float* conv_b = (const float*)d_in[2];
    const float* w_ih   = (const float*)d_in[3];
    const float* w_hh   = (const float*)d_in[4];
    const float* b_ih   = (const float*)d_in[5];
    const float* b_hh   = (const float*)d_in[6];
    float* out = (float*)d_out;

    __half *glu, *h0, *h1, *wihp, *whhp, *convwt, *wcomb;
    short *z;
    float *c, *bsum, *bcomb;
    cudaGetSymbolAddress((void**)&glu,    g_glu);
    cudaGetSymbolAddress((void**)&z,      g_z);
    cudaGetSymbolAddress((void**)&h0,     g_h0);
    cudaGetSymbolAddress((void**)&h1,     g_h1);
    cudaGetSymbolAddress((void**)&c,      g_c);
    cudaGetSymbolAddress((void**)&wihp,   g_wih_p);
    cudaGetSymbolAddress((void**)&whhp,   g_whh_p);
    cudaGetSymbolAddress((void**)&convwt, g_convw_t);
    cudaGetSymbolAddress((void**)&wcomb,  g_wcomb);
    cudaGetSymbolAddress((void**)&bcomb,  g_bcomb);
    cudaGetSymbolAddress((void**)&bsum,   g_bsum);

    static int smem_set = 0;
    if (!smem_set) {
        cudaFuncSetAttribute(gemm_mma<0>, cudaFuncAttributeMaxDynamicSharedMemorySize, GEMM_SMEM);
        cudaFuncSetAttribute(gemm_mma<1>, cudaFuncAttributeMaxDynamicSharedMemorySize, GEMM_SMEM);
        cudaFuncSetAttribute(gemm_mma<3>, cudaFuncAttributeMaxDynamicSharedMemorySize, GEMM_SMEM);
        smem_set = 1;
    }

    // 0. merged weight prep (incl. bias_comb)
    prep_kernel<<<(PREP_TOTAL + 255) / 256, 256>>>(
        w_ih, w_hh, conv_w, conv_b, b_ih, b_hh, wihp, whhp, convwt, bsum, bcomb);

    // 1. GLU -> fp16
    glu_kernel<<<(S_ROWS * D_HALF / 4 + 255) / 256, 256>>>(x, glu);

    // 2. W_comb = w_ih_p @ conv_w  (2048x256, K=512) -> fp16
    gemm_mma<1><<<dim3(D_HALF / 128, G4 / 128), 256, GEMM_SMEM>>>(
        wihp, convwt, wcomb, D_HALF, D_MODEL, nullptr,
        nullptr, nullptr, nullptr, nullptr, nullptr, nullptr, 0, 0);

    // 3. z = glu @ W_comb^T + bias_comb (K=256) -> int16, PLUS fused step 0
    gemm_mma<3><<<dim3(G4 / 128, S_ROWS / 128), 256, GEMM_SMEM>>>(
        glu, wcomb, z, G4, D_HALF, bcomb,
        nullptr, bsum, nullptr, c, h0, nullptr, 0, 1);

    // 4. steps 1..8: fused recurrent GEMM + LSTM cell, ping-pong h buffers
    __half* hb[2] = {h0, h1};
    for (int k = 1; k <= 8; k++) {
        const __half* h_in = hb[(k - 1) & 1];
        __half* hh = (k == 8) ? nullptr : hb[k & 1];
        float*  hf = (k == 8) ? out : nullptr;
        gemm_mma<0><<<dim3(G4 / 128, S_ROWS / 128), 256, GEMM_SMEM>>>(
            h_in, whhp, nullptr, G4, D_MODEL, nullptr,
            z, bsum, c, c, hh, hf, k, (k < 8) ? 1 : 0);
    }
}

// round 17
// speedup vs baseline: 1.4304x; 1.4304x over previous
#include <cuda_runtime.h>
#include <cuda_fp16.h>
#include <cstdint>
#include <cstddef>

// Problem dims (fixed)
#define S_ROWS  8192      // B*L = 16*512
#define D_MODEL 512
#define D_HALF  256
#define G4      2048      // 4*D_MODEL

#define ZSCALE  2048.0f
#define ZINV    (1.0f / 2048.0f)

// ---------------------------------------------------------------------------
// Scratch (static device arrays — no runtime allocation)
// ---------------------------------------------------------------------------
__device__ __half g_glu[S_ROWS * D_HALF];
__device__ short  g_z[(size_t)S_ROWS * G4];     // gate-interleaved, int16 x2048
__device__ __half g_h0[S_ROWS * D_MODEL];       // ping-pong h buffers (no WAR race)
__device__ __half g_h1[S_ROWS * D_MODEL];
__device__ float  g_c[S_ROWS * D_MODEL];
__device__ __half g_wih_p[G4 * D_MODEL];        // permuted fp16 w_ih
__device__ __half g_whh_p[G4 * D_MODEL];        // permuted fp16 w_hh
__device__ __half g_convw_t[D_HALF * D_MODEL];  // conv_w^T fp16 [c, d]
__device__ __half g_wcomb[G4 * D_HALF];         // w_ih_p @ conv_w  (fp16)
__device__ float  g_bcomb[G4];                  // w_ih·conv_b + b_ih + b_hh (permuted)
__device__ float  g_bsum[G4];                   // b_ih + b_hh, permuted (fp32)

// ---------------------------------------------------------------------------
// Helpers (base PTX only)
// ---------------------------------------------------------------------------
__device__ __forceinline__ uint32_t smem_u32(const void* p) {
    uint32_t a;
    asm("{ .reg .u64 t; cvta.to.shared.u64 t, %1; cvt.u32.u64 %0, t; }" : "=r"(a) : "l"(p));
    return a;
}
__device__ __forceinline__ void cp16(uint32_t dst, const void* src) {
    asm volatile("cp.async.cg.shared.global [%0], [%1], 16;" :: "r"(dst), "l"(src) : "memory");
}
__device__ __forceinline__ void cp_commit() {
    asm volatile("cp.async.commit_group;" ::: "memory");
}
template <int N>
__device__ __forceinline__ void cp_wait() {
    asm volatile("cp.async.wait_group %0;" :: "n"(N) : "memory");
}
__device__ __forceinline__ void ldsm_x4(uint32_t& r0, uint32_t& r1, uint32_t& r2, uint32_t& r3,
                                        uint32_t addr) {
    asm volatile("ldmatrix.sync.aligned.m8n8.x4.shared.b16 {%0,%1,%2,%3}, [%4];"
                 : "=r"(r0), "=r"(r1), "=r"(r2), "=r"(r3) : "r"(addr));
}

// m16n8k16 fp16 MMA, fp32 accumulate: D = A*B + D
__device__ __forceinline__ void mma_f16(float c[4], const uint32_t a[4], const uint32_t b[2]) {
    asm volatile(
        "mma.sync.aligned.m16n8k16.row.col.f32.f16.f16.f32 "
        "{%0,%1,%2,%3}, {%4,%5,%6,%7}, {%8,%9}, {%0,%1,%2,%3};"
        : "+f"(c[0]), "+f"(c[1]), "+f"(c[2]), "+f"(c[3])
        : "r"(a[0]), "r"(a[1]), "r"(a[2]), "r"(a[3]), "r"(b[0]), "r"(b[1]));
}

__device__ __forceinline__ float sigm(float x) { return 1.f / (1.f + __expf(-x)); }
__device__ __forceinline__ short zq(float v) {
    return (short)__float2int_rn(fminf(fmaxf(v, -15.9f), 15.9f) * ZSCALE);
}

// ---------------------------------------------------------------------------
// fp16 tensor-core GEMM (TN): C[m,n] = sum_k A[m*K+k] * Bw[n*K+k] (+bias)
// Block 128x128, 8 warps (2 M x 4 N), warp tile 64x32, BK=64 halves,
// 3-stage cp.async with ONE __syncthreads per panel (proven R12/R15 pipeline
// — the R16 mbarrier variant lost 45% to try_wait polling), ldmatrix,
// 2 CTAs/SM.
// Template MODE selects the epilogue at COMPILE TIME (keeps hot MODE 0
// under the 128-reg cap):
//   MODE 0: fused LSTM cell (steps 1..8); MODE 1: plain fp16 C;
//   MODE 3: int16 z + fused LSTM step 0.
// PDL=true (mode 0 only): programmatic dependent launch — pre-load the
// independent B operand (w_hh, written long before) for stages 0/1, then
// cudaGridDependencySynchronize(), then the dependent A (=h) loads.
// Gate-interleaved B/z layout (col n' = 4d + gate). h_out must not alias A.
// ---------------------------------------------------------------------------
#define BK      64                     // halves per K panel
#define ROW32   36                     // uint32 per smem row (32 data + 4 pad)
#define STAGE32 ((128 + 128) * ROW32)  // 9216 uint32 per stage
#define GEMM_SMEM (3 * STAGE32 * 4)    // 110592 bytes
#define GTS     136                    // epilogue gate-tile row stride (floats)

template <int MODE, bool PDL>
__global__ __launch_bounds__(256, 2)
void gemm_mma(const __half* __restrict__ A, const __half* __restrict__ Bw,
              void* __restrict__ C, int Nt, int K,
              const float* __restrict__ bias,
              const short* __restrict__ z, const float* __restrict__ bsum,
              const float* __restrict__ c_in, float* __restrict__ c_out,
              __half* __restrict__ h_out_h, float* __restrict__ h_out_f,
              int step, int write_c)
{
    extern __shared__ uint32_t sm32[];
    const int tid  = threadIdx.x;
    const int lane = tid & 31;
    const int wid  = tid >> 5;
    const int g    = lane >> 2;
    const int ctg  = lane & 3;
    const int wm   = (wid & 1) * 64;      // 2 warps along M
    const int wn   = (wid >> 1) * 32;     // 4 warps along N
    const int bm   = blockIdx.y * 128;
    const int bn   = blockIdx.x * 128;
    const int KT   = K / BK;
    const uint32_t sb = smem_u32(sm32);

    // ldmatrix per-lane address offsets (uint32 units) — validated R10/R11
    const uint32_t a_off32 = (uint32_t)(wm + (lane & 7) + ((lane >> 3) & 1) * 8) * ROW32
                           + ((lane >> 4) & 1) * 4;
    const uint32_t b_off32 = (uint32_t)(128 + wn + (lane & 7) + ((lane >> 4) & 1) * 8) * ROW32
                           + ((lane >> 3) & 1) * 4;

    auto load_stage_A = [&](int kt, int s) {
        const int k0 = kt * BK;
        const uint32_t ab = sb + (uint32_t)s * STAGE32 * 4;
        #pragma unroll
        for (int i = 0; i < 4; i++) {            // A: 128 rows x 8 granules(16B)
            int idx = tid + i * 256;
            int r = idx >> 3, cc = idx & 7;
            cp16(ab + (uint32_t)(r * ROW32 + cc * 4) * 4,
                 A + (size_t)(bm + r) * K + k0 + cc * 8);
        }
    };
    auto load_stage_B = [&](int kt, int s) {
        const int k0 = kt * BK;
        const uint32_t bb = sb + (uint32_t)s * STAGE32 * 4 + 128 * ROW32 * 4;
        #pragma unroll
        for (int i = 0; i < 4; i++) {            // B: 128 rows x 8 granules
            int idx = tid + i * 256;
            int r = idx >> 3, cc = idx & 7;
            cp16(bb + (uint32_t)(r * ROW32 + cc * 4) * 4,
                 Bw + (size_t)(bn + r) * K + k0 + cc * 8);
        }
    };
    auto load_stage = [&](int kt, int s) { load_stage_A(kt, s); load_stage_B(kt, s); };

    float acc[4][4][4];
    #pragma unroll
    for (int mi = 0; mi < 4; mi++)
        #pragma unroll
        for (int ni = 0; ni < 4; ni++)
            #pragma unroll
            for (int t = 0; t < 4; t++) acc[mi][ni][t] = 0.f;

    if constexpr (PDL) {
        // B operand (w_hh) is stable long before this launch: prefetch it
        // while the previous step's kernel is still draining, then wait for
        // the dependent data (A = h, c) before touching it.
        load_stage_B(0, 0);
        load_stage_B(1, 1);
#if defined(__CUDA_ARCH__) && __CUDA_ARCH__ >= 900
        cudaGridDependencySynchronize();
#endif
        load_stage_A(0, 0); cp_commit();      // group0 = {B0, B1, A0}
        load_stage_A(1, 1); cp_commit();      // group1 = {A1}
    } else {
        load_stage(0, 0); cp_commit();
        load_stage(1, 1); cp_commit();
    }

    for (int kt = 0; kt < KT; kt++) {
        cp_wait<1>();                  // stage kt landed (newest pending: kt+1)
        __syncthreads();               // data visible AND stage kt-1 buffer free
        if (kt + 2 < KT) load_stage(kt + 2, (kt + 2) % 3);
        cp_commit();                   // uniform group count

        const uint32_t stage_addr = sb + (uint32_t)(kt % 3) * STAGE32 * 4;
        const uint32_t a_addr = stage_addr + a_off32 * 4;
        const uint32_t b_addr = stage_addr + b_off32 * 4;

        #pragma unroll
        for (int ks = 0; ks < 4; ks++) {          // 4 x k16 per panel
            uint32_t af[4][4], bf[4][2];
            #pragma unroll
            for (int mi = 0; mi < 4; mi++)
                ldsm_x4(af[mi][0], af[mi][1], af[mi][2], af[mi][3],
                        a_addr + (uint32_t)(mi * 16 * ROW32 + ks * 8) * 4);
            #pragma unroll
            for (int j = 0; j < 2; j++)
                ldsm_x4(bf[2 * j][0], bf[2 * j][1], bf[2 * j + 1][0], bf[2 * j + 1][1],
                        b_addr + (uint32_t)(j * 16 * ROW32 + ks * 8) * 4);
            #pragma unroll
            for (int mi = 0; mi < 4; mi++)
                #pragma unroll
                for (int ni = 0; ni < 4; ni++)
                    mma_f16(acc[mi][ni], af[mi], bf[ni]);
        }
    }

    if constexpr (MODE == 0) {
        // ---- fused LSTM epilogue (steps 1..8) ----
        __syncthreads();               // all warps done with stage buffers
        float* smf = (float*)sm32;
        #pragma unroll
        for (int ni = 0; ni < 4; ni++) {
            const int cl = wn + ni * 8 + 2 * ctg;
            #pragma unroll
            for (int mi = 0; mi < 4; mi++) {
                const int rl = wm + mi * 16 + g;
                *(float2*)(smf + (size_t)rl * GTS + cl)       = make_float2(acc[mi][ni][0], acc[mi][ni][1]);
                *(float2*)(smf + (size_t)(rl + 8) * GTS + cl) = make_float2(acc[mi][ni][2], acc[mi][ni][3]);
            }
        }
        __syncthreads();

        const int dn0 = bn >> 2;                     // 32 hidden units per N tile
        #pragma unroll
        for (int it = 0; it < 16; it++) {
            int idx = it * 256 + tid;
            int rl = idx >> 5, dl = idx & 31;
            int s = bm + rl, d = dn0 + dl;
            int l = s & 511, t = l - 8 + step;

            float4 gz;
            if (t >= 0) {
                short4 q = *(const short4*)(z + (size_t)(s - 8 + step) * G4 + 4 * d);
                gz = make_float4(q.x * ZINV, q.y * ZINV, q.z * ZINV, q.w * ZINV);
            } else {
                gz = *(const float4*)(bsum + 4 * d);
            }

            float4 gr = *(const float4*)(smf + (size_t)rl * GTS + 4 * dl);
            float gi = gz.x + gr.x;
            float gf = gz.y + gr.y;
            float gg = gz.z + gr.z;
            float go = gz.w + gr.w;

            float c_prev = c_in[(size_t)s * D_MODEL + d];
            float cn = sigm(gf) * c_prev + sigm(gi) * tanhf(gg);
            float hn = sigm(go) * tanhf(cn);
            if (write_c) c_out[(size_t)s * D_MODEL + d] = cn;
            if (h_out_h) h_out_h[(size_t)s * D_MODEL + d] = __float2half_rn(hn);
            else         h_out_f[(size_t)s * D_MODEL + d] = hn;
        }
    } else if constexpr (MODE == 3) {
        // ---- z-production epilogue + fused LSTM step 0 ----
        __syncthreads();               // stage buffers free
        float* smf = (float*)sm32;
        #pragma unroll
        for (int ni = 0; ni < 4; ni++) {
            const int cl = wn + ni * 8 + 2 * ctg;
            #pragma unroll
            for (int mi = 0; mi < 4; mi++) {
                const int rl = wm + mi * 16 + g;
                *(float2*)(smf + (size_t)rl * GTS + cl)       = make_float2(acc[mi][ni][0], acc[mi][ni][1]);
                *(float2*)(smf + (size_t)(rl + 8) * GTS + cl) = make_float2(acc[mi][ni][2], acc[mi][ni][3]);
            }
        }
        __syncthreads();

        short* Cs = (short*)C;
        const int dn0 = bn >> 2;
        #pragma unroll
        for (int it = 0; it < 16; it++) {
            int idx = it * 256 + tid;
            int rl = idx >> 5, dl = idx & 31;
            int row = bm + rl, d = dn0 + dl;

            float4 gr = *(const float4*)(smf + (size_t)rl * GTS + 4 * dl);
            float4 bb = *(const float4*)(bias + 4 * d);
            float gi = gr.x + bb.x;
            float gf = gr.y + bb.y;
            float gg = gr.z + bb.z;
            float go = gr.w + bb.w;

            // write int16 z (used by steps 1..8)
            short4 q = make_short4(zq(gi), zq(gf), zq(gg), zq(go));
            *(short4*)(Cs + (size_t)row * Nt + 4 * d) = q;

            // fused step 0 for sequence s = row + 8 (same batch only)
            if ((row & 511) < 504) {
                int s = row + 8;
                float cn = sigm(gi) * tanhf(gg);
                float hn = sigm(go) * tanhf(cn);
                c_out[(size_t)s * D_MODEL + d] = cn;
                h_out_h[(size_t)s * D_MODEL + d] = __float2half_rn(hn);
            }
        }
        // sequences with l < 8: step 0 input is zero-padded -> bias-only gates
        if ((bm & 511) == 0) {
            int rl = tid >> 5, dl = tid & 31;     // 8 rows x 32 d
            int s = bm + rl, d = dn0 + dl;
            float4 gz = *(const float4*)(bsum + 4 * d);
            float cn = sigm(gz.x) * tanhf(gz.z);
            float hn = sigm(gz.w) * tanhf(cn);
            c_out[(size_t)s * D_MODEL + d] = cn;
            h_out_h[(size_t)s * D_MODEL + d] = __float2half_rn(hn);
        }
    } else {
        // ---- MODE 1: plain epilogue: bias, write fp16 ----
        #pragma unroll
        for (int ni = 0; ni < 4; ni++) {
            const int col = bn + wn + ni * 8 + 2 * ctg;
            float b0 = 0.f, b1 = 0.f;
            if (bias) { b0 = bias[col]; b1 = bias[col + 1]; }
            #pragma unroll
            for (int mi = 0; mi < 4; mi++) {
                const int row = bm + wm + mi * 16 + g;
                float v0 = acc[mi][ni][0] + b0;
                float v1 = acc[mi][ni][1] + b1;
                float v2 = acc[mi][ni][2] + b0;
                float v3 = acc[mi][ni][3] + b1;
                __half* Ch = (__half*)C;
                *(__half2*)(Ch + (size_t)row * Nt + col)       = __floats2half2_rn(v0, v1);
                *(__half2*)(Ch + (size_t)(row + 8) * Nt + col) = __floats2half2_rn(v2, v3);
            }
        }
    }
}

// ---------------------------------------------------------------------------
// Merged prep kernel: permute+convert recurrent weights to fp16, transpose
// conv_w to fp16 [c, d], bsum, and bias_comb (warp dot-products) — one launch.
// ---------------------------------------------------------------------------
#define WSEG   (G4 * D_MODEL / 4)          // 262144 float4 per weight matrix
#define CSEG   (D_HALF * D_MODEL / 4)      // 32768 (transposed conv, 4 d per item)
#define BSEG   (G4 / 4)                    // 512
#define BCSEG  (G4 * 32)                   // 65536 (one warp per bias_comb entry)
#define PREP_TOTAL (2 * WSEG + CSEG + BSEG + BCSEG)

__global__ void prep_kernel(const float* __restrict__ w_ih, const float* __restrict__ w_hh,
                            const float* __restrict__ conv_w, const float* __restrict__ conv_b,
                            const float* __restrict__ b_ih, const float* __restrict__ b_hh,
                            __half* __restrict__ wihp, __half* __restrict__ whhp,
                            __half* __restrict__ convwt, float* __restrict__ bsum,
                            float* __restrict__ bcomb)
{
    int i = blockIdx.x * blockDim.x + threadIdx.x;
    if (i >= PREP_TOTAL) return;

    if (i < 2 * WSEG) {
        const float* src = (i < WSEG) ? w_ih : w_hh;
        __half* dst = (i < WSEG) ? wihp : whhp;
        int j = (i < WSEG) ? i : i - WSEG;
        int np = j >> 7;                 // dst row (0..2047)
        int c4 = (j & 127) * 4;
        int d = np >> 2, gg = np & 3;
        float4 v = *(const float4*)(src + (size_t)(gg * D_MODEL + d) * D_MODEL + c4);
        __half* o = dst + (size_t)np * D_MODEL + c4;
        *(__half2*)(o)     = __floats2half2_rn(v.x, v.y);
        *(__half2*)(o + 2) = __floats2half2_rn(v.z, v.w);
    } else if (i < 2 * WSEG + CSEG) {
        int j = i - 2 * WSEG;
        int cc = j >> 7;                 // 0..255
        int d0 = (j & 127) * 4;          // 0..508
        float v0 = conv_w[(size_t)(d0 + 0) * D_HALF + cc];
        float v1 = conv_w[(size_t)(d0 + 1) * D_HALF + cc];
        float v2 = conv_w[(size_t)(d0 + 2) * D_HALF + cc];
        float v3 = conv_w[(size_t)(d0 + 3) * D_HALF + cc];
        __half* o = convwt + (size_t)cc * D_MODEL + d0;
        *(__half2*)(o)     = __floats2half2_rn(v0, v1);
        *(__half2*)(o + 2) = __floats2half2_rn(v2, v3);
    } else if (i < 2 * WSEG + CSEG + BSEG) {
        int j = i - 2 * WSEG - CSEG;     // 4 bsum entries
        #pragma unroll
        for (int t = 0; t < 4; t++) {
            int np = j * 4 + t;
            int d = np >> 2, gg = np & 3;
            bsum[np] = b_ih[gg * D_MODEL + d] + b_hh[gg * D_MODEL + d];
        }
    } else {
        // bias_comb: one warp per np (segment base is warp-aligned)
        int j = i - (2 * WSEG + CSEG + BSEG);
        int np = j >> 5;
        int lane = j & 31;
        int dd = np >> 2, gg = np & 3;
        const float* wr = w_ih + (size_t)(gg * D_MODEL + dd) * D_MODEL;
        float s = 0.f;
        #pragma unroll 4
        for (int d = lane; d < D_MODEL; d += 32) s += wr[d] * conv_b[d];
        #pragma unroll
        for (int o = 16; o; o >>= 1) s += __shfl_xor_sync(0xffffffffu, s, o);
        if (lane == 0) bcomb[np] = s + b_ih[gg * D_MODEL + dd] + b_hh[gg * D_MODEL + dd];
    }
}

// ---------------------------------------------------------------------------
// GLU: out[s,c] = fp16(a * sigmoid(b))
// ---------------------------------------------------------------------------
__global__ void glu_kernel(const float* __restrict__ x, __half* __restrict__ out)
{
    int idx = blockIdx.x * blockDim.x + threadIdx.x;
    if (idx >= S_ROWS * D_HALF / 4) return;
    int row = idx / (D_HALF / 4);
    int c4  = (idx % (D_HALF / 4)) * 4;
    const float* xr = x + (size_t)row * D_MODEL;
    float4 a = *(const float4*)(xr + c4);
    float4 b = *(const float4*)(xr + D_HALF + c4);
    __half* o = out + (size_t)row * D_HALF + c4;
    *(__half2*)(o)     = __floats2half2_rn(a.x * sigm(b.x), a.y * sigm(b.y));
    *(__half2*)(o + 2) = __floats2half2_rn(a.z * sigm(b.z), a.w * sigm(b.w));
}

// ---------------------------------------------------------------------------
// Launcher
// ---------------------------------------------------------------------------
extern "C" void kernel_launch(void* const* d_in, const int* in_sizes, int n_in,
                              void* d_out, int out_size)
{
    const float* x      = (const float*)d_in[0];
    const float* conv_w = (const float*)d_in[1];
    const float* conv_b = (const float*)d_in[2];
    const float* w_ih   = (const float*)d_in[3];
    const float* w_hh   = (const float*)d_in[4];
    const float* b_ih   = (const float*)d_in[5];
    const float* b_hh   = (const float*)d_in[6];
    float* out = (float*)d_out;

    __half *glu, *h0, *h1, *wihp, *whhp, *convwt, *wcomb;
    short *z;
    float *c, *bsum, *bcomb;
    cudaGetSymbolAddress((void**)&glu,    g_glu);
    cudaGetSymbolAddress((void**)&z,      g_z);
    cudaGetSymbolAddress((void**)&h0,     g_h0);
    cudaGetSymbolAddress((void**)&h1,     g_h1);
    cudaGetSymbolAddress((void**)&c,      g_c);
    cudaGetSymbolAddress((void**)&wihp,   g_wih_p);
    cudaGetSymbolAddress((void**)&whhp,   g_whh_p);
    cudaGetSymbolAddress((void**)&convwt, g_convw_t);
    cudaGetSymbolAddress((void**)&wcomb,  g_wcomb);
    cudaGetSymbolAddress((void**)&bcomb,  g_bcomb);
    cudaGetSymbolAddress((void**)&bsum,   g_bsum);

    static int smem_set = 0;
    if (!smem_set) {
        cudaFuncSetAttribute(gemm_mma<0, true>,  cudaFuncAttributeMaxDynamicSharedMemorySize, GEMM_SMEM);
        cudaFuncSetAttribute(gemm_mma<1, false>, cudaFuncAttributeMaxDynamicSharedMemorySize, GEMM_SMEM);
        cudaFuncSetAttribute(gemm_mma<3, false>, cudaFuncAttributeMaxDynamicSharedMemorySize, GEMM_SMEM);
        smem_set = 1;
    }

    // 0. merged weight prep (incl. bias_comb)
    prep_kernel<<<(PREP_TOTAL + 255) / 256, 256>>>(
        w_ih, w_hh, conv_w, conv_b, b_ih, b_hh, wihp, whhp, convwt, bsum, bcomb);

    // 1. GLU -> fp16
    glu_kernel<<<(S_ROWS * D_HALF / 4 + 255) / 256, 256>>>(x, glu);

    // 2. W_comb = w_ih_p @ conv_w  (2048x256, K=512) -> fp16
    gemm_mma<1, false><<<dim3(D_HALF / 128, G4 / 128), 256, GEMM_SMEM>>>(
        wihp, convwt, wcomb, D_HALF, D_MODEL, nullptr,
        nullptr, nullptr, nullptr, nullptr, nullptr, nullptr, 0, 0);

    // 3. z = glu @ W_comb^T + bias_comb (K=256) -> int16, PLUS fused step 0
    gemm_mma<3, false><<<dim3(G4 / 128, S_ROWS / 128), 256, GEMM_SMEM>>>(
        glu, wcomb, z, G4, D_HALF, bcomb,
        nullptr, bsum, nullptr, c, h0, nullptr, 0, 1);

    // 4. steps 1..8: fused recurrent GEMM + LSTM cell, ping-pong h buffers,
    //    PDL launches (w_hh prefetch overlaps the previous step's tail).
    cudaLaunchConfig_t cfg = {};
    cfg.gridDim  = dim3(G4 / 128, S_ROWS / 128);
    cfg.blockDim = dim3(256, 1, 1);
    cfg.dynamicSmemBytes = GEMM_SMEM;
    cfg.stream = 0;
    cudaLaunchAttribute attrs[1];
    attrs[0].id = cudaLaunchAttributeProgrammaticStreamSerialization;
    attrs[0].val.programmaticStreamSerializationAllowed = 1;
    cfg.attrs = attrs;
    cfg.numAttrs = 1;

    __half* hb[2] = {h0, h1};
    for (int k = 1; k <= 8; k++) {
        const __half* h_in = hb[(k - 1) & 1];
        __half* hh = (k == 8) ? nullptr : hb[k & 1];
        float*  hf = (k == 8) ? out : nullptr;
        cudaLaunchKernelEx(&cfg, gemm_mma<0, true>,
                           h_in, (const __half*)whhp, (void*)nullptr, (int)G4, (int)D_MODEL,
                           (const float*)nullptr,
                           (const short*)z, (const float*)bsum,
                           (const float*)c, (float*)c, hh, hf,
                           (int)k, (int)((k < 8) ? 1 : 0));
    }
}